// round 5
// baseline (speedup 1.0000x reference)
#include <cuda_runtime.h>

static constexpr int NB  = 8;    // batch
static constexpr int NN  = 96;   // nodes
static constexpr int ND  = 16;   // feature dim
static constexpr int H0  = 50;
static constexpr int H1  = 50;
static constexpr int NOUT = 64;
#define NEG_SLOPE 0.05f

// Scratch (device globals: no allocation allowed in kernel_launch)
__device__ float g_dis  [NB*NN*NN];   // dis[b,i,j]
__device__ float g_sdikT[NB*NN*NN];   // sdikT[b,j,i] = sum_k adj[b,j,k]*dis[b,i,k] (dis symmetric)
__device__ float g_A    [NB*NN*H0];   // x @ W1[0:16]
__device__ float g_Bm   [NB*NN*H0];   // x @ W1[16:32]
__device__ float g_C    [NB*NN*H0];   // x @ W1[32:48]
__device__ float g_sumC [NB*NN*H0];   // adj @ C
__device__ float g_deg  [NB*NN];
__device__ float g_sd   [NB*NN];      // sum_j adj[i,j]*dis[i,j]
__device__ float g_aggx [NB*NN*ND];   // adj @ x

__device__ __forceinline__ float leaky(float v) { return v >= 0.f ? v : NEG_SLOPE * v; }

// ---------------------------------------------------------------------------
// k1: per (b,i) block, 96 threads.
// Computes dis row i, deg_i, sd_i, (adj@x) row i, and A/Bm/C rows for node i.
// ---------------------------------------------------------------------------
__global__ void k1(const float* __restrict__ x, const float* __restrict__ adj,
                   const float* __restrict__ W1) {
    const int i = blockIdx.x, b = blockIdx.y;
    const int tid = threadIdx.x;                 // 0..95
    __shared__ float sx[NN * ND];                // full x[b] tile (6 KB)
    __shared__ float sdis[NN], sadj[NN];
    __shared__ float pa[3], pd[3];

    const float* xb = x + b * NN * ND;
    #pragma unroll
    for (int k = 0; k < ND; k++) sx[tid + k * NN] = xb[tid + k * NN];  // linear copy
    __syncthreads();

    // dis[i, tid]
    {
        float acc = 1e-10f;
        #pragma unroll
        for (int d = 0; d < ND; d++) {
            float df = sx[i * ND + d] - sx[tid * ND + d];
            acc += df * df;
        }
        float dv = sqrtf(acc);
        sdis[tid] = dv;
        g_dis[(b * NN + i) * NN + tid] = dv;
        sadj[tid] = adj[(b * NN + i) * NN + tid];
    }
    __syncthreads();

    // deg_i, sd_i via warp reductions (96 = 3 full warps)
    {
        float va = sadj[tid];
        float vd = va * sdis[tid];
        #pragma unroll
        for (int off = 16; off; off >>= 1) {
            va += __shfl_down_sync(0xffffffffu, va, off);
            vd += __shfl_down_sync(0xffffffffu, vd, off);
        }
        int w = tid >> 5, lane = tid & 31;
        if (lane == 0) { pa[w] = va; pd[w] = vd; }
    }
    __syncthreads();
    if (tid == 0) {
        g_deg[b * NN + i] = pa[0] + pa[1] + pa[2];
        g_sd [b * NN + i] = pd[0] + pd[1] + pd[2];
    }

    // aggx row i = sum_j adj[i,j] * x[j,:]
    if (tid < ND) {
        float acc = 0.f;
        for (int j = 0; j < NN; j++) {
            float a = sadj[j];
            if (a != 0.f) acc += a * sx[j * ND + tid];
        }
        g_aggx[(b * NN + i) * ND + tid] = acc;
    }

    // A / Bm / C rows for node i (thread = output channel h)
    if (tid < H0) {
        float a = 0.f, bm = 0.f, c = 0.f;
        #pragma unroll
        for (int d = 0; d < ND; d++) {
            float xv = sx[i * ND + d];
            a  += xv * W1[d * H0 + tid];
            bm += xv * W1[(ND + d) * H0 + tid];
            c  += xv * W1[(2 * ND + d) * H0 + tid];
        }
        g_A [(b * NN + i) * H0 + tid] = a;
        g_Bm[(b * NN + i) * H0 + tid] = bm;
        g_C [(b * NN + i) * H0 + tid] = c;
    }
}

// ---------------------------------------------------------------------------
// k2: per (b,j) block, 96 threads. Needs all of g_dis / g_C from k1.
// sumC[b,j,:] = adj[b,j,:] @ C[b]
// sdikT[b,j,i] = sum_k adj[b,j,k] * dis[b,k,i]   (== sd_ik[b,i,j], dis symmetric)
// ---------------------------------------------------------------------------
__global__ void k2(const float* __restrict__ adj) {
    const int j = blockIdx.x, b = blockIdx.y;
    const int tid = threadIdx.x;                 // 0..95
    __shared__ float sadj[NN];
    sadj[tid] = adj[(b * NN + j) * NN + tid];
    __syncthreads();

    // sdikT row (thread = i, coalesced dis column reads)
    {
        float acc = 0.f;
        const float* disb = g_dis + b * NN * NN;
        for (int k = 0; k < NN; k++) {
            float a = sadj[k];
            if (a != 0.f) acc += a * disb[k * NN + tid];
        }
        g_sdikT[(b * NN + j) * NN + tid] = acc;
    }
    // sumC row (thread = h, coalesced C row reads)
    if (tid < H0) {
        float acc = 0.f;
        const float* Cb = g_C + b * NN * H0;
        for (int k = 0; k < NN; k++) {
            float a = sadj[k];
            if (a != 0.f) acc += a * Cb[k * H0 + tid];
        }
        g_sumC[(b * NN + j) * H0 + tid] = acc;
    }
}

// ---------------------------------------------------------------------------
// k3: per (b,i) block, 64 threads. Main edge loop + epilogue.
//
// m2_sum[i,h1] = leaky( deg_i*(x_i@W2a + b2)[h1] + (aggx_i@W2b)[h1] + sd_i*W2dis[h1]
//                       + sum_{j: adj!=0} a_ij * leaky(a_ij * S_ij) @ W2m3 [h1] )
// S_ij[h0] = deg_j*(A_i + Bm_j + b1 + dis_ij*w_ij)[h0] + sumC_j[h0]
//            + sd_j*w_jk[h0] + sdik_ij*w_ik[h0]
// out[i,:] = leaky( [x_i, m2_sum_i] @ W3 + b3 )
// ---------------------------------------------------------------------------
__global__ void k3(const float* __restrict__ x, const float* __restrict__ adj,
                   const float* __restrict__ W1, const float* __restrict__ b1,
                   const float* __restrict__ W2, const float* __restrict__ b2,
                   const float* __restrict__ W3, const float* __restrict__ b3,
                   float* __restrict__ out) {
    const int i = blockIdx.x, b = blockIdx.y;
    const int tid = threadIdx.x;                 // 0..63
    const int bi = b * NN + i;

    __shared__ float sW[H0 * H1];                // W2 m3-block (rows 33..82), 10 KB
    __shared__ float st[H0];
    __shared__ float sdisr[NN], sadjr[NN];
    __shared__ float sxi[ND], sax[ND];
    __shared__ float sm2[H1];

    // W2 rows [2D+1 .. 2D+H0] are contiguous: copy once into shared
    for (int idx = tid; idx < H0 * H1; idx += 64)
        sW[idx] = W2[(2 * ND + 1) * H1 + idx];
    for (int idx = tid; idx < NN; idx += 64) {
        sdisr[idx] = g_dis[bi * NN + idx];
        sadjr[idx] = adj[bi * NN + idx];
    }
    if (tid < ND) { sxi[tid] = x[bi * ND + tid]; sax[tid] = g_aggx[bi * ND + tid]; }

    float rA = 0.f, rwij = 0.f, rwjk = 0.f, rwik = 0.f, acc = 0.f;
    if (tid < H0) {
        rA   = g_A[bi * H0 + tid] + b1[tid];
        rwij = W1[(3 * ND    ) * H0 + tid];
        rwjk = W1[(3 * ND + 1) * H0 + tid];
        rwik = W1[(3 * ND + 2) * H0 + tid];
    }
    __syncthreads();

    // Edge loop (branch is uniform across the block: a comes from shared)
    for (int j = 0; j < NN; j++) {
        float a = sadjr[j];
        if (a == 0.f) continue;
        if (tid < H0) {
            const int bj = b * NN + j;
            float degj = g_deg[bj];
            float sdj  = g_sd[bj];
            float dij  = sdisr[j];
            float sdik = g_sdikT[bj * NN + i];
            float S = degj * (rA + g_Bm[bj * H0 + tid] + dij * rwij)
                    + g_sumC[bj * H0 + tid] + sdj * rwjk + sdik * rwik;
            float as = a * S;
            st[tid] = a * leaky(as);
        }
        __syncthreads();
        if (tid < H0) {
            #pragma unroll
            for (int h = 0; h < H0; h++)
                acc += st[h] * sW[h * H1 + tid];
        }
        __syncthreads();
    }

    // Factored linear terms + leaky -> m2_sum
    if (tid < H1) {
        float degi = g_deg[bi], sdi = g_sd[bi];
        float s1 = 0.f, s2 = 0.f;
        #pragma unroll
        for (int d = 0; d < ND; d++) {
            s1 += sxi[d] * W2[d * H1 + tid];
            s2 += sax[d] * W2[(ND + d) * H1 + tid];
        }
        acc += degi * (s1 + b2[tid]) + s2 + sdi * W2[(2 * ND) * H1 + tid];
        sm2[tid] = leaky(acc);
    }
    __syncthreads();

    // Output GEMV: thread = output channel (NOUT == 64 == blockDim)
    {
        float s = b3[tid];
        #pragma unroll
        for (int d = 0; d < ND; d++) s += sxi[d] * W3[d * NOUT + tid];
        #pragma unroll 10
        for (int h = 0; h < H1; h++) s += sm2[h] * W3[(ND + h) * NOUT + tid];
        out[bi * NOUT + tid] = leaky(s);
    }
}

extern "C" void kernel_launch(void* const* d_in, const int* in_sizes, int n_in,
                              void* d_out, int out_size) {
    const float* x   = (const float*)d_in[0];
    const float* adj = (const float*)d_in[1];
    const float* W1  = (const float*)d_in[2];
    const float* b1  = (const float*)d_in[3];
    const float* W2  = (const float*)d_in[4];
    const float* b2  = (const float*)d_in[5];
    const float* W3  = (const float*)d_in[6];
    const float* b3  = (const float*)d_in[7];
    float* out = (float*)d_out;

    dim3 grid(NN, NB);
    k1<<<grid, NN>>>(x, adj, W1);
    k2<<<grid, NN>>>(adj);
    k3<<<grid, 64>>>(x, adj, W1, b1, W2, b2, W3, b3, out);
}

// round 8
// speedup vs baseline: 2.3976x; 2.3976x over previous
#include <cuda_runtime.h>

static constexpr int NB   = 8;    // batch
static constexpr int NN   = 96;   // nodes
static constexpr int ND   = 16;   // feature dim
static constexpr int H0   = 50;
static constexpr int H1   = 50;
static constexpr int NOUT = 64;
static constexpr int XS   = 17;   // padded x stride (bank-conflict-free)
#define NEG_SLOPE 0.05f

// Scratch (device globals: no allocation allowed in kernel_launch)
__device__ float g_dis  [NB*NN*NN];   // dis[b,i,j]
__device__ float g_sdikT[NB*NN*NN];   // sdikT[b,j,i] = sum_k adj[b,j,k]*dis[b,i,k]
__device__ float g_A    [NB*NN*H0];   // x @ W1[0:16]
__device__ float g_C    [NB*NN*H0];   // x @ W1[32:48]
__device__ float g_F    [NB*NN*H0];   // deg_j*(b1+Bm_j) + sd_j*w_jk
__device__ float g_E    [NB*NN*H0];   // F_j + adj_j @ C
__device__ float g_deg  [NB*NN];
__device__ float g_sd   [NB*NN];
__device__ float g_aggx [NB*NN*ND];   // adj @ x

__device__ __forceinline__ float leaky(float v) { return v >= 0.f ? v : NEG_SLOPE * v; }

// ---------------------------------------------------------------------------
// k1: per (b,i) block, 96 threads.
// dis row, deg, sd, adj@x row, A/C rows, and F row (fused Bm+bias+w_jk term).
// ---------------------------------------------------------------------------
__global__ void k1(const float* __restrict__ x, const float* __restrict__ adj,
                   const float* __restrict__ W1, const float* __restrict__ b1) {
    const int i = blockIdx.x, b = blockIdx.y;
    const int tid = threadIdx.x;                 // 0..95
    __shared__ float sx[NN * XS];                // padded: conflict-free
    __shared__ float sadj[NN];
    __shared__ float red[6];

    const float* xb = x + b * NN * ND;
    #pragma unroll
    for (int t = 0; t < ND; t++) {
        int idx = tid + t * NN;                  // coalesced read
        sx[(idx >> 4) * XS + (idx & 15)] = xb[idx];
    }
    __syncthreads();

    // dis[i, tid]
    float acc = 1e-10f;
    #pragma unroll
    for (int d = 0; d < ND; d++) {
        float df = sx[i * XS + d] - sx[tid * XS + d];
        acc += df * df;
    }
    float dv = sqrtf(acc);
    g_dis[(b * NN + i) * NN + tid] = dv;
    float av = adj[(b * NN + i) * NN + tid];
    sadj[tid] = av;

    // deg_i, sd_i: butterfly within warp, combine 3 warps through shared
    {
        float va = av, vd = av * dv;
        #pragma unroll
        for (int off = 16; off; off >>= 1) {
            va += __shfl_xor_sync(0xffffffffu, va, off);
            vd += __shfl_xor_sync(0xffffffffu, vd, off);
        }
        int w = tid >> 5;
        if ((tid & 31) == 0) { red[w] = va; red[3 + w] = vd; }
    }
    __syncthreads();
    const float degv = red[0] + red[1] + red[2];
    const float sdv  = red[3] + red[4] + red[5];
    if (tid == 0) { g_deg[b * NN + i] = degv; g_sd[b * NN + i] = sdv; }

    // aggx row i = sum_j adj[i,j] * x[j,:]
    if (tid < ND) {
        float s = 0.f;
        for (int j = 0; j < NN; j++) {
            float a = sadj[j];
            if (a != 0.f) s += a * sx[j * XS + tid];
        }
        g_aggx[(b * NN + i) * ND + tid] = s;
    }

    // A / C / F rows for node i (thread = output channel h)
    if (tid < H0) {
        float a0 = 0.f, bm = 0.f, c = 0.f;
        #pragma unroll
        for (int d = 0; d < ND; d++) {
            float xv = sx[i * XS + d];
            a0 += xv * W1[d * H0 + tid];
            bm += xv * W1[(ND + d) * H0 + tid];
            c  += xv * W1[(2 * ND + d) * H0 + tid];
        }
        const int bi = b * NN + i;
        g_A[bi * H0 + tid] = a0;
        g_C[bi * H0 + tid] = c;
        g_F[bi * H0 + tid] = degv * (b1[tid] + bm) + sdv * W1[(3 * ND + 1) * H0 + tid];
    }
}

// ---------------------------------------------------------------------------
// k2: per (b,j) block, 96 threads. Deterministic ballot compaction of adj row.
// sdikT[b,j,:] and E[b,j,:] = F[b,j,:] + adj[b,j,:] @ C[b]
// ---------------------------------------------------------------------------
__global__ void k2(const float* __restrict__ adj) {
    const int j = blockIdx.x, b = blockIdx.y;
    const int tid = threadIdx.x;                 // 0..95
    __shared__ float sadj[NN];
    __shared__ int sjidx[NN];
    __shared__ int wc[3];

    float a = adj[(b * NN + j) * NN + tid];
    sadj[tid] = a;
    unsigned m = __ballot_sync(0xffffffffu, a != 0.f);
    int w = tid >> 5, lane = tid & 31;
    if (lane == 0) wc[w] = __popc(m);
    __syncthreads();
    int base = (w > 0 ? wc[0] : 0) + (w > 1 ? wc[1] : 0);
    if (a != 0.f) sjidx[base + __popc(m & ((1u << lane) - 1u))] = tid;
    const int n = wc[0] + wc[1] + wc[2];
    __syncthreads();

    // sdikT row (thread = i, coalesced dis column reads)
    {
        float acc = 0.f;
        const float* disb = g_dis + b * NN * NN;
        #pragma unroll 4
        for (int e = 0; e < n; e++) {
            int k = sjidx[e];
            acc += sadj[k] * disb[k * NN + tid];
        }
        g_sdikT[(b * NN + j) * NN + tid] = acc;
    }
    // E row (thread = h)
    if (tid < H0) {
        float acc = g_F[(b * NN + j) * H0 + tid];
        const float* Cb = g_C + b * NN * H0;
        #pragma unroll 4
        for (int e = 0; e < n; e++) {
            int k = sjidx[e];
            acc += sadj[k] * Cb[k * H0 + tid];
        }
        g_E[(b * NN + j) * H0 + tid] = acc;
    }
}

// ---------------------------------------------------------------------------
// k3: per (b,i) block, 96 threads. Barrier-free edge loop:
//   tsum[h] = sum_{j in nbrs} a * leaky(a * S_ij[h]),
//   S_ij[h] = deg_j*A_i[h] + (deg_j*dij)*w_ij[h] + sdik*w_ik[h] + E_j[h]
// then ONE 50x50 matvec: m3 contribution = tsum @ W2m3.
// ---------------------------------------------------------------------------
__global__ void k3(const float* __restrict__ x, const float* __restrict__ adj,
                   const float* __restrict__ W1, const float* __restrict__ W2,
                   const float* __restrict__ b2, const float* __restrict__ W3,
                   const float* __restrict__ b3, float* __restrict__ out) {
    const int i = blockIdx.x, b = blockIdx.y;
    const int tid = threadIdx.x;                 // 0..95
    const int bi = b * NN + i;

    __shared__ float sW[H0 * H1];                // W2 m3-block (10 KB)
    __shared__ float sdisr[NN], sadjr[NN];
    __shared__ int sjidx[NN];
    __shared__ int wc[3];
    __shared__ float sxi[ND], sax[ND];
    __shared__ float stsum[H0], sm2[H1];

    for (int idx = tid; idx < H0 * H1; idx += NN)
        sW[idx] = W2[(2 * ND + 1) * H1 + idx];

    float a = adj[bi * NN + tid];
    sadjr[tid] = a;
    sdisr[tid] = g_dis[bi * NN + tid];
    unsigned m = __ballot_sync(0xffffffffu, a != 0.f);
    int w = tid >> 5, lane = tid & 31;
    if (lane == 0) wc[w] = __popc(m);
    if (tid < ND) { sxi[tid] = x[bi * ND + tid]; sax[tid] = g_aggx[bi * ND + tid]; }

    float rA = 0.f, rwij = 0.f, rwik = 0.f;
    if (tid < H0) {
        rA   = g_A[bi * H0 + tid];
        rwij = W1[(3 * ND    ) * H0 + tid];
        rwik = W1[(3 * ND + 2) * H0 + tid];
    }
    __syncthreads();
    int base = (w > 0 ? wc[0] : 0) + (w > 1 ? wc[1] : 0);
    if (a != 0.f) sjidx[base + __popc(m & ((1u << lane) - 1u))] = tid;
    const int n = wc[0] + wc[1] + wc[2];
    __syncthreads();

    // Edge loop: no barriers, each thread owns h = tid of tsum.
    if (tid < H0) {
        float tsum = 0.f;
        #pragma unroll 2
        for (int e = 0; e < n; e++) {
            int j = sjidx[e];
            int bj = b * NN + j;
            float av   = sadjr[j];
            float dij  = sdisr[j];
            float degj = g_deg[bj];
            float sdik = g_sdikT[bj * NN + i];
            float E    = g_E[bj * H0 + tid];
            float S = fmaf(degj, rA, fmaf(degj * dij, rwij, fmaf(sdik, rwik, E)));
            tsum += av * leaky(av * S);
        }
        stsum[tid] = tsum;
    }
    __syncthreads();

    // Single matvec + factored linear terms -> m2_sum
    if (tid < H1) {
        float acc = 0.f;
        #pragma unroll
        for (int h = 0; h < H0; h++)
            acc += stsum[h] * sW[h * H1 + tid];
        float degi = g_deg[bi], sdi = g_sd[bi];
        float s1 = 0.f, s2 = 0.f;
        #pragma unroll
        for (int d = 0; d < ND; d++) {
            s1 += sxi[d] * W2[d * H1 + tid];
            s2 += sax[d] * W2[(ND + d) * H1 + tid];
        }
        acc += degi * (s1 + b2[tid]) + s2 + sdi * W2[(2 * ND) * H1 + tid];
        sm2[tid] = leaky(acc);
    }
    __syncthreads();

    // Output GEMV (thread = output channel)
    if (tid < NOUT) {
        float s = b3[tid];
        #pragma unroll
        for (int d = 0; d < ND; d++) s += sxi[d] * W3[d * NOUT + tid];
        #pragma unroll 10
        for (int h = 0; h < H1; h++) s += sm2[h] * W3[(ND + h) * NOUT + tid];
        out[bi * NOUT + tid] = leaky(s);
    }
}

extern "C" void kernel_launch(void* const* d_in, const int* in_sizes, int n_in,
                              void* d_out, int out_size) {
    const float* x   = (const float*)d_in[0];
    const float* adj = (const float*)d_in[1];
    const float* W1  = (const float*)d_in[2];
    const float* b1  = (const float*)d_in[3];
    const float* W2  = (const float*)d_in[4];
    const float* b2  = (const float*)d_in[5];
    const float* W3  = (const float*)d_in[6];
    const float* b3  = (const float*)d_in[7];
    float* out = (float*)d_out;

    dim3 grid(NN, NB);
    k1<<<grid, NN>>>(x, adj, W1, b1);
    k2<<<grid, NN>>>(adj);
    k3<<<grid, NN>>>(x, adj, W1, W2, b2, W3, b3, out);
}